// round 17
// baseline (speedup 1.0000x reference)
#include <cuda_runtime.h>
#include <cuda_bf16.h>
#include <cuda_fp16.h>
#include <cstdint>

#define TSTEPS 500
#define BATCH  64
#define INDIM  440
#define INPAD  448
#define HID    1024
#define OUTDIM 1944
#define ROWS   (TSTEPS * BATCH)   // 32000

// ---------------------------------------------------------------------------
// Scratch (static device globals; no runtime allocation allowed)
// ---------------------------------------------------------------------------
__device__ __align__(16) __nv_bfloat16 g_actB[(size_t)ROWS * HID];  // spikes (bf16, exact)
__device__ __align__(16) __half        g_actH[(size_t)ROWS * HID];  // spikes (fp16, exact)
__device__ __align__(16) float         g_ws  [(size_t)ROWS * HID];  // pre-scan dense outputs
__device__ __align__(16) __nv_bfloat16 g_W0hi[HID * INPAD];
__device__ __align__(16) __nv_bfloat16 g_W0lo[HID * INPAD];
__device__ __align__(16) __half        g_Wsh [3 * HID * HID];       // layers 1,2,3 fp16
__device__ __align__(16) __half        g_Wfh [OUTDIM * HID];        // final fp16

// ---------------------------------------------------------------------------
// Weight split: w -> bf16 hi + bf16 lo (residual), with K padding zeroed
// ---------------------------------------------------------------------------
__global__ void split_weights_kernel(const float* __restrict__ W,
                                     __nv_bfloat16* __restrict__ hi,
                                     __nv_bfloat16* __restrict__ lo,
                                     int rows, int cols, int colsPad) {
    long long idx = (long long)blockIdx.x * blockDim.x + threadIdx.x;
    long long total = (long long)rows * colsPad;
    if (idx >= total) return;
    int r = (int)(idx / colsPad);
    int c = (int)(idx % colsPad);
    float w = (c < cols) ? W[(long long)r * cols + c] : 0.0f;
    __nv_bfloat16 h = __float2bfloat16(w);
    hi[idx] = h;
    lo[idx] = __float2bfloat16(w - __bfloat162float(h));
}

// float -> fp16 (round to nearest), contiguous
__global__ void to_half_kernel(const float* __restrict__ W, __half* __restrict__ H,
                               long long total) {
    long long idx = (long long)blockIdx.x * blockDim.x + threadIdx.x;
    if (idx < total) H[idx] = __float2half_rn(W[idx]);
}

// ---------------------------------------------------------------------------
// Input FSQ scan: vmem += x; q = clip(rint(vmem),0,7); out=q; vmem -= q
// ---------------------------------------------------------------------------
__global__ void __launch_bounds__(128)
input_scan_kernel(const float* __restrict__ xs, __nv_bfloat16* __restrict__ act) {
    int tid = blockIdx.x * blockDim.x + threadIdx.x;
    if (tid >= BATCH * INPAD) return;
    int b = tid / INPAD, i = tid % INPAD;
    __nv_bfloat16* op = act + (size_t)b * INPAD + i;
    const int strideO = BATCH * INPAD;
    if (i >= INDIM) {
        __nv_bfloat16 z = __float2bfloat16(0.0f);
        for (int t = 0; t < TSTEPS; t++) op[t * strideO] = z;
        return;
    }
    const float* xp = xs + (size_t)b * INDIM + i;
    const int strideX = BATCH * INDIM;
    float vmem = 0.0f;
#define ISTEP(X, TT) { vmem = __fadd_rn(vmem, (X)); \
        float q = fminf(7.0f, fmaxf(0.0f, rintf(vmem))); \
        op[(TT) * strideO] = __float2bfloat16(q); \
        vmem = __fsub_rn(vmem, q); }
    int t = 0;
    for (; t + 8 <= TSTEPS; t += 8) {
        float x[8];
#pragma unroll
        for (int j = 0; j < 8; j++) x[j] = xp[(t + j) * strideX];
#pragma unroll
        for (int j = 0; j < 8; j++) ISTEP(x[j], t + j)
    }
    for (; t < TSTEPS; t++) { float x = xp[t * strideX]; ISTEP(x, t) }
#undef ISTEP
}

// ---------------------------------------------------------------------------
// LIF scan: syn = w + tau*syn; vmem += syn; q = clip(rint(vmem),0,7); vmem -= q
// ---------------------------------------------------------------------------
__global__ void __launch_bounds__(128)
lif_scan_kernel(const float* __restrict__ ws, const float* __restrict__ taus,
                __half* __restrict__ act) {
    int tid = blockIdx.x * blockDim.x + threadIdx.x;
    if (tid >= BATCH * HID) return;
    int b = tid / HID, h = tid % HID;
    float tau = taus[h];
    const float* wp = ws + (size_t)b * HID + h;
    __half* op = act + (size_t)b * HID + h;
    const int stride = BATCH * HID;
    float syn = 0.0f, vmem = 0.0f;
#define LSTEP(W, TT) { syn = __fadd_rn((W), __fmul_rn(tau, syn)); \
        vmem = __fadd_rn(vmem, syn); \
        float q = fminf(7.0f, fmaxf(0.0f, rintf(vmem))); \
        op[(TT) * stride] = __float2half_rn(q); \
        vmem = __fsub_rn(vmem, q); }
    int t = 0;
    for (; t + 8 <= TSTEPS; t += 8) {
        float w[8];
#pragma unroll
        for (int j = 0; j < 8; j++) w[j] = wp[(t + j) * stride];
#pragma unroll
        for (int j = 0; j < 8; j++) LSTEP(w[j], t + j)
    }
    for (; t < TSTEPS; t++) { float w = wp[t * stride]; LSTEP(w, t) }
#undef LSTEP
}

// ---------------------------------------------------------------------------
// Common GEMM building blocks
// ---------------------------------------------------------------------------
#define BK 32
#define GSTAGES 3
#define LDS_ROW 40                           // 16-bit elems per smem row (32 + 8 pad)
#define A_TILE_BYTES  (128 * LDS_ROW * 2)    // 10240 (128 rows)
#define B1_TILE_BYTES (128 * LDS_ROW * 2)    // 10240 (128 rows, dual kernel)
#define B2_TILE_BYTES (256 * LDS_ROW * 2)    // 20480 (256 rows, wide kernel)

__device__ __forceinline__ void cp_async16(uint32_t dst, const void* src, bool pred) {
    int bytes = pred ? 16 : 0;
    asm volatile("cp.async.cg.shared.global [%0], [%1], 16, %2;\n"
                 :: "r"(dst), "l"(src), "r"(bytes));
}
__device__ __forceinline__ void ldm4(uint32_t* r, uint32_t addr) {
    asm volatile("ldmatrix.sync.aligned.m8n8.x4.shared.b16 {%0,%1,%2,%3}, [%4];\n"
                 : "=r"(r[0]), "=r"(r[1]), "=r"(r[2]), "=r"(r[3]) : "r"(addr));
}
template <bool F16>
__device__ __forceinline__ void mma16816(float* c, const uint32_t* a, uint32_t b0, uint32_t b1) {
    if constexpr (F16) {
        asm volatile("mma.sync.aligned.m16n8k16.row.col.f32.f16.f16.f32 "
                     "{%0,%1,%2,%3}, {%4,%5,%6,%7}, {%8,%9}, {%0,%1,%2,%3};\n"
                     : "+f"(c[0]), "+f"(c[1]), "+f"(c[2]), "+f"(c[3])
                     : "r"(a[0]), "r"(a[1]), "r"(a[2]), "r"(a[3]), "r"(b0), "r"(b1));
    } else {
        asm volatile("mma.sync.aligned.m16n8k16.row.col.f32.bf16.bf16.f32 "
                     "{%0,%1,%2,%3}, {%4,%5,%6,%7}, {%8,%9}, {%0,%1,%2,%3};\n"
                     : "+f"(c[0]), "+f"(c[1]), "+f"(c[2]), "+f"(c[3])
                     : "r"(a[0]), "r"(a[1]), "r"(a[2]), "r"(a[3]), "r"(b0), "r"(b1));
    }
}

// ---------------------------------------------------------------------------
// DUAL GEMM (layer 0): 128x128 CTA, bf16 hi+lo, proven R6 body.
// ---------------------------------------------------------------------------
#define STAGE_BYTES_D (3 * A_TILE_BYTES)     // A | Bhi | Blo
#define SMEM_DUAL (GSTAGES * STAGE_BYTES_D)  // 92160

__global__ void __launch_bounds__(256)
gemm_bn_dual(const uint16_t* __restrict__ A,
             const uint16_t* __restrict__ Bhi,
             const uint16_t* __restrict__ Blo,
             float* __restrict__ C,
             int N, int K,
             const float* __restrict__ gamma,
             const float* __restrict__ beta) {
    extern __shared__ __align__(16) uint16_t smem_buf[];
    const int tid = threadIdx.x;
    const int lane = tid & 31, warp = tid >> 5;
    const int wm = warp >> 1;
    const int wn = warp & 1;
    const int m0 = blockIdx.x * 128;
    const int n0 = blockIdx.y * 128;
    const int KT = K / BK;
    const uint32_t sbase = (uint32_t)__cvta_generic_to_shared(smem_buf);

    const int lm   = lane & 7;
    const int mat  = lane >> 3;
    const int roff = ((mat & 1) << 3) | lm;
    const int koff = (mat >> 1) << 3;

    float acc[2][8][4] = {};

    auto issue_stage = [&](int kt, int s) {
        if (kt < KT) {
            const int kk = kt * BK;
            const uint32_t sA  = sbase + s * STAGE_BYTES_D;
            const uint32_t sBh = sA + A_TILE_BYTES;
            const uint32_t sBl = sBh + B1_TILE_BYTES;
#pragma unroll
            for (int i = 0; i < 2; i++) {
                int c = tid + i * 256;
                int r = c >> 2, col = c & 3;
                uint32_t dst = sA + (uint32_t)(r * LDS_ROW + col * 8) * 2;
                cp_async16(dst, A + (size_t)(m0 + r) * K + kk + col * 8, true);
            }
#pragma unroll
            for (int i = 0; i < 2; i++) {
                int c = tid + i * 256;
                int r = c >> 2, col = c & 3;
                uint32_t dst = sBh + (uint32_t)(r * LDS_ROW + col * 8) * 2;
                cp_async16(dst, Bhi + (size_t)(n0 + r) * K + kk + col * 8, true);
                uint32_t dstl = sBl + (uint32_t)(r * LDS_ROW + col * 8) * 2;
                cp_async16(dstl, Blo + (size_t)(n0 + r) * K + kk + col * 8, true);
            }
        }
        asm volatile("cp.async.commit_group;\n" ::);
    };

    auto compute_stage = [&](int s) {
        const uint32_t aB  = sbase + s * STAGE_BYTES_D;
        const uint32_t bhB = aB + A_TILE_BYTES;
        const uint32_t blB = bhB + B1_TILE_BYTES;
#pragma unroll
        for (int k16 = 0; k16 < 2; k16++) {
            uint32_t afr[2][4];
#pragma unroll
            for (int mi = 0; mi < 2; mi++)
                ldm4(afr[mi], aB + (uint32_t)((wm * 32 + mi * 16 + roff) * LDS_ROW + k16 * 16 + koff) * 2);
#pragma unroll
            for (int nj = 0; nj < 4; nj++) {
                uint32_t boff = (uint32_t)((wn * 64 + nj * 16 + roff) * LDS_ROW + k16 * 16 + koff) * 2;
                uint32_t bfr[4];
                ldm4(bfr, bhB + boff);
                mma16816<false>(acc[0][2 * nj + 0], afr[0], bfr[0], bfr[2]);
                mma16816<false>(acc[1][2 * nj + 0], afr[1], bfr[0], bfr[2]);
                mma16816<false>(acc[0][2 * nj + 1], afr[0], bfr[1], bfr[3]);
                mma16816<false>(acc[1][2 * nj + 1], afr[1], bfr[1], bfr[3]);
                uint32_t lfr[4];
                ldm4(lfr, blB + boff);
                mma16816<false>(acc[0][2 * nj + 0], afr[0], lfr[0], lfr[2]);
                mma16816<false>(acc[1][2 * nj + 0], afr[1], lfr[0], lfr[2]);
                mma16816<false>(acc[0][2 * nj + 1], afr[0], lfr[1], lfr[3]);
                mma16816<false>(acc[1][2 * nj + 1], afr[1], lfr[1], lfr[3]);
            }
        }
    };

#pragma unroll
    for (int s = 0; s < GSTAGES - 1; s++) issue_stage(s, s);
    for (int kt = 0; kt < KT; kt++) {
        asm volatile("cp.async.wait_group 1;\n" ::);
        __syncthreads();
        compute_stage(kt % GSTAGES);
        issue_stage(kt + GSTAGES - 1, (kt + GSTAGES - 1) % GSTAGES);
    }
    asm volatile("cp.async.wait_group 0;\n" ::);

    const float inv = rsqrtf(1.0f + 1e-5f);
    const int qr = lane >> 2;
    const int qc = (lane & 3) << 1;
#pragma unroll
    for (int ni = 0; ni < 8; ni++) {
        int n = n0 + wn * 64 + ni * 8 + qc;
        float g0 = gamma[n] * inv, b0 = beta[n];
        float g1 = gamma[n + 1] * inv, b1 = beta[n + 1];
#pragma unroll
        for (int mi = 0; mi < 2; mi++) {
#pragma unroll
            for (int h = 0; h < 2; h++) {
                int row = m0 + wm * 32 + mi * 16 + qr + h * 8;
                float v0 = fmaf(acc[mi][ni][h * 2 + 0], g0, b0);
                float v1 = fmaf(acc[mi][ni][h * 2 + 1], g1, b1);
                *reinterpret_cast<float2*>(C + (size_t)row * N + n) = make_float2(v0, v1);
            }
        }
    }
}

// ---------------------------------------------------------------------------
// WIDE single-B GEMM: 128x256 CTA tile, fp16, warp tile 64x64 (8 warps 2x4).
// Better A-fragment reuse -> mma-bound instead of smem-bound.
// ---------------------------------------------------------------------------
#define STAGE_BYTES_W (A_TILE_BYTES + B2_TILE_BYTES)  // 30720
#define SMEM_WIDE (GSTAGES * STAGE_BYTES_W)           // 92160

__global__ void __launch_bounds__(256, 1)
gemm_bn_wide(const uint16_t* __restrict__ A,
             const uint16_t* __restrict__ B,
             float* __restrict__ C,
             int N, int K,
             const float* __restrict__ gamma,
             const float* __restrict__ beta) {
    extern __shared__ __align__(16) uint16_t smem_buf[];
    const int tid = threadIdx.x;
    const int lane = tid & 31, warp = tid >> 5;
    const int wm = warp >> 2;       // 0..1 -> 64 rows of M each
    const int wn = warp & 3;        // 0..3 -> 64 cols of N each
    const int m0 = blockIdx.x * 128;
    const int n0 = blockIdx.y * 256;
    const int KT = K / BK;
    const uint32_t sbase = (uint32_t)__cvta_generic_to_shared(smem_buf);

    const int lm   = lane & 7;
    const int mat  = lane >> 3;
    const int roff = ((mat & 1) << 3) | lm;
    const int koff = (mat >> 1) << 3;

    float acc[4][8][4] = {};   // [mi 16-row][nj8 8-col][frag]

    auto issue_stage = [&](int kt, int s) {
        if (kt < KT) {
            const int kk = kt * BK;
            const uint32_t sA = sbase + s * STAGE_BYTES_W;
            const uint32_t sB = sA + A_TILE_BYTES;
#pragma unroll
            for (int i = 0; i < 2; i++) {        // A: 128 rows
                int c = tid + i * 256;
                int r = c >> 2, col = c & 3;
                uint32_t dst = sA + (uint32_t)(r * LDS_ROW + col * 8) * 2;
                cp_async16(dst, A + (size_t)(m0 + r) * K + kk + col * 8, true);
            }
#pragma unroll
            for (int i = 0; i < 4; i++) {        // B: 256 rows
                int c = tid + i * 256;
                int r = c >> 2, col = c & 3;
                bool pred = (n0 + r) < N;
                int rr = pred ? (n0 + r) : 0;
                uint32_t dst = sB + (uint32_t)(r * LDS_ROW + col * 8) * 2;
                cp_async16(dst, B + (size_t)rr * K + kk + col * 8, pred);
            }
        }
        asm volatile("cp.async.commit_group;\n" ::);
    };

    auto compute_stage = [&](int s) {
        const uint32_t aB = sbase + s * STAGE_BYTES_W;
        const uint32_t bB = aB + A_TILE_BYTES;
#pragma unroll
        for (int k16 = 0; k16 < 2; k16++) {
            uint32_t afr[4][4];
#pragma unroll
            for (int mi = 0; mi < 4; mi++)
                ldm4(afr[mi], aB + (uint32_t)((wm * 64 + mi * 16 + roff) * LDS_ROW + k16 * 16 + koff) * 2);
#pragma unroll
            for (int nj = 0; nj < 4; nj++) {
                uint32_t boff = (uint32_t)((wn * 64 + nj * 16 + roff) * LDS_ROW + k16 * 16 + koff) * 2;
                uint32_t bfr[4];
                ldm4(bfr, bB + boff);
#pragma unroll
                for (int mi = 0; mi < 4; mi++) {
                    mma16816<true>(acc[mi][2 * nj + 0], afr[mi], bfr[0], bfr[2]);
                    mma16816<true>(acc[mi][2 * nj + 1], afr[mi], bfr[1], bfr[3]);
                }
            }
        }
    };

#pragma unroll
    for (int s = 0; s < GSTAGES - 1; s++) issue_stage(s, s);
    for (int kt = 0; kt < KT; kt++) {
        asm volatile("cp.async.wait_group 1;\n" ::);
        __syncthreads();
        compute_stage(kt % GSTAGES);
        issue_stage(kt + GSTAGES - 1, (kt + GSTAGES - 1) % GSTAGES);
    }
    asm volatile("cp.async.wait_group 0;\n" ::);

    // Epilogue: BN fused, fp32 stores, predicated on n < N
    const float inv = rsqrtf(1.0f + 1e-5f);
    const int qr = lane >> 2;
    const int qc = (lane & 3) << 1;
#pragma unroll
    for (int ni = 0; ni < 8; ni++) {
        int n = n0 + wn * 64 + ni * 8 + qc;
        if (n >= N) continue;
        float g0 = gamma[n] * inv, b0 = beta[n];
        bool has2 = (n + 1 < N);
        float g1 = has2 ? gamma[n + 1] * inv : 0.0f;
        float b1 = has2 ? beta[n + 1] : 0.0f;
#pragma unroll
        for (int mi = 0; mi < 4; mi++) {
#pragma unroll
            for (int h = 0; h < 2; h++) {
                int row = m0 + wm * 64 + mi * 16 + qr + h * 8;
                float v0 = fmaf(acc[mi][ni][h * 2 + 0], g0, b0);
                float v1 = fmaf(acc[mi][ni][h * 2 + 1], g1, b1);
                float* cp = C + (size_t)row * N + n;
                if (has2) *reinterpret_cast<float2*>(cp) = make_float2(v0, v1);
                else      cp[0] = v0;
            }
        }
    }
}

// ---------------------------------------------------------------------------
// log-softmax over rows of [ROWS, OUTDIM], in place
// ---------------------------------------------------------------------------
__global__ void __launch_bounds__(256) logsoftmax_kernel(float* __restrict__ out) {
    __shared__ float sv[OUTDIM];
    __shared__ float red[9];
    const int tid = threadIdx.x, lane = tid & 31, warp = tid >> 5;
    float* p = out + (size_t)blockIdx.x * OUTDIM;

    float mx = -3.4e38f;
    for (int i = tid; i < OUTDIM; i += 256) { float v = p[i]; sv[i] = v; mx = fmaxf(mx, v); }
#pragma unroll
    for (int o = 16; o; o >>= 1) mx = fmaxf(mx, __shfl_xor_sync(0xffffffffu, mx, o));
    if (lane == 0) red[warp] = mx;
    __syncthreads();
    if (warp == 0) {
        float v = (lane < 8) ? red[lane] : -3.4e38f;
#pragma unroll
        for (int o = 4; o; o >>= 1) v = fmaxf(v, __shfl_xor_sync(0xffffffffu, v, o));
        if (lane == 0) red[8] = v;
    }
    __syncthreads();
    mx = red[8];

    float s = 0.0f;
    for (int i = tid; i < OUTDIM; i += 256) s += expf(sv[i] - mx);
#pragma unroll
    for (int o = 16; o; o >>= 1) s += __shfl_xor_sync(0xffffffffu, s, o);
    __syncthreads();
    if (lane == 0) red[warp] = s;
    __syncthreads();
    if (warp == 0) {
        float v = (lane < 8) ? red[lane] : 0.0f;
#pragma unroll
        for (int o = 4; o; o >>= 1) v += __shfl_xor_sync(0xffffffffu, v, o);
        if (lane == 0) red[8] = v;
    }
    __syncthreads();
    float lse = mx + logf(red[8]);
    for (int i = tid; i < OUTDIM; i += 256) p[i] = sv[i] - lse;
}

// ---------------------------------------------------------------------------
// Launch sequence
// ---------------------------------------------------------------------------
extern "C" void kernel_launch(void* const* d_in, const int* in_sizes, int n_in,
                              void* d_out, int out_size) {
    const float* xs   = (const float*)d_in[0];   // [500,64,440]
    const float* W0   = (const float*)d_in[1];   // [1024,440]
    const float* Ws   = (const float*)d_in[2];   // [3,1024,1024]
    const float* taus = (const float*)d_in[3];   // [4,1024]
    const float* bng  = (const float*)d_in[4];   // [4,1024]
    const float* bnb  = (const float*)d_in[5];   // [4,1024]
    const float* Wf   = (const float*)d_in[6];   // [1944,1024]
    const float* fg   = (const float*)d_in[7];   // [1944]
    const float* fb   = (const float*)d_in[8];   // [1944]
    float* out = (float*)d_out;

    void* p;
    cudaGetSymbolAddress(&p, g_actB); uint16_t* actB = (uint16_t*)p;
    cudaGetSymbolAddress(&p, g_actH); uint16_t* actH = (uint16_t*)p;
    cudaGetSymbolAddress(&p, g_ws);   float*    ws   = (float*)p;
    cudaGetSymbolAddress(&p, g_W0hi); uint16_t* w0hi = (uint16_t*)p;
    cudaGetSymbolAddress(&p, g_W0lo); uint16_t* w0lo = (uint16_t*)p;
    cudaGetSymbolAddress(&p, g_Wsh);  uint16_t* wsh  = (uint16_t*)p;
    cudaGetSymbolAddress(&p, g_Wfh);  uint16_t* wfh  = (uint16_t*)p;

    cudaFuncSetAttribute((const void*)gemm_bn_dual,
                         cudaFuncAttributeMaxDynamicSharedMemorySize, SMEM_DUAL);
    cudaFuncSetAttribute((const void*)gemm_bn_wide,
                         cudaFuncAttributeMaxDynamicSharedMemorySize, SMEM_WIDE);

    // --- weight preparation (idempotent) ---
    split_weights_kernel<<<(HID * INPAD + 255) / 256, 256>>>(
        W0, (__nv_bfloat16*)w0hi, (__nv_bfloat16*)w0lo, HID, INDIM, INPAD);
    to_half_kernel<<<(3 * HID * HID + 255) / 256, 256>>>(
        Ws, (__half*)wsh, (long long)3 * HID * HID);
    to_half_kernel<<<((long long)OUTDIM * HID + 255) / 256, 256>>>(
        Wf, (__half*)wfh, (long long)OUTDIM * HID);

    // --- input FSQ scan -> actB [32000, 448] bf16 ---
    input_scan_kernel<<<(BATCH * INPAD + 127) / 128, 128>>>(xs, (__nv_bfloat16*)actB);

    // layer 0 (bf16 hi+lo dual, 128x128) -> spikes in fp16
    dim3 g0(ROWS / 128, HID / 128);   // (250, 8)
    gemm_bn_dual<<<g0, 256, SMEM_DUAL>>>(actB, w0hi, w0lo, ws, HID, INPAD, bng, bnb);
    lif_scan_kernel<<<(BATCH * HID) / 128, 128>>>(ws, taus, (__half*)actH);

    // layers 1..3 (fp16 single, 128x256 wide)
    dim3 gw(ROWS / 128, HID / 256);   // (250, 4)
    for (int l = 1; l < 4; l++) {
        gemm_bn_wide<<<gw, 256, SMEM_WIDE>>>(
            actH, wsh + (size_t)(l - 1) * HID * HID,
            ws, HID, HID, bng + l * HID, bnb + l * HID);
        lif_scan_kernel<<<(BATCH * HID) / 128, 128>>>(
            ws, taus + l * HID, (__half*)actH);
    }

    // final projection (fp16 single, wide) -> d_out [32000, 1944] fp32
    dim3 gf(ROWS / 128, (OUTDIM + 255) / 256);  // (250, 8)
    gemm_bn_wide<<<gf, 256, SMEM_WIDE>>>(actH, wfh, out, OUTDIM, HID, fg, fb);

    // in-place log-softmax per row
    logsoftmax_kernel<<<ROWS, 256>>>(out);
}